// round 1
// baseline (speedup 1.0000x reference)
#include <cuda_runtime.h>
#include <cstdint>

#define BB 16
#define HH 256
#define WW 256
#define HWSZ (HH * WW)            // 65536
#define NPIX (BB * HWSZ)          // 1048576

// ---------------- scratch (device globals: no allocation allowed) ----------
__device__ float g_masked[NPIX];   // neg ? score : +inf
__device__ float g_clsloss[NPIX];  // per-pixel 2-class CE
// accumulators: 0:Sw(ce*weight) 1:L1num 2:L1den 3:L0num 4:L0den 5:Ssel(ce*sel)
__device__ double g_acc[6];
__device__ int g_npos[BB];
__device__ int g_nneg[BB];
__device__ unsigned long long g_nsel;
__device__ float g_thr[BB];

__device__ __forceinline__ float posinf() { return __uint_as_float(0x7f800000u); }

// ---------------- kernel 0: zero accumulators ------------------------------
__global__ void k_zero() {
    int t = threadIdx.x;
    if (t < 6) g_acc[t] = 0.0;
    if (t < BB) { g_npos[t] = 0; g_nneg[t] = 0; }
    if (t == 0) g_nsel = 0ull;
}

// ---------------- kernel 1: pointwise pass ---------------------------------
// 256 threads/block, 4096 blocks; every block lies within one batch image.
__global__ __launch_bounds__(256) void k_pass1(const float* __restrict__ target,
                                               const float* __restrict__ logits) {
    const int i  = blockIdx.x * blockDim.x + threadIdx.x;   // pixel index
    const int b  = i / HWSZ;
    const int hw = i - b * HWSZ;

    const float* tp = target + (size_t)i * 10;
    const float lab = tp[0];
    const float wt  = tp[1];
    const bool pos = lab > 0.0f;
    const bool neg = lab == 0.0f;

    const float* lg = logits + (size_t)b * 10 * HWSZ + hw;
    const float z0 = lg[0];
    const float z1 = lg[HWSZ];
    {
        // nothing
    }
    const float m    = fmaxf(z0, z1);
    const float e0   = __expf(z0 - m);
    const float e1   = __expf(z1 - m);
    const float den  = e0 + e1;
    const float score = e0 / den;
    const float logd  = __logf(den);
    const float cls_ce = -((pos ? z1 : z0) - m - logd);

    g_masked[i]  = neg ? score : posinf();
    g_clsloss[i] = cls_ce;

    float sw = cls_ce * wt;

    // link loss: class-0 logit = channel 2+n, class-1 logit = channel 6+n
    float l1n = 0.f, l1d = 0.f, l0n = 0.f, l0d = 0.f;
#pragma unroll
    for (int n = 0; n < 4; n++) {
        const float a  = lg[(2 + n) * HWSZ];
        const float c  = lg[(6 + n) * HWSZ];
        const float mm = fmaxf(a, c);
        const float ld = __logf(__expf(a - mm) + __expf(c - mm));
        const int   li = (int)tp[2 + n];        // 0 or 1
        const float lw = tp[6 + n];
        const float ce = -(((li != 0) ? c : a) - mm - ld);
        if (li != 0) { l1n += ce * lw; l1d += lw; }
        else         { l0n += ce * lw; l0d += lw; }
    }

    // -------- block reduction: 5 float sums + 2 counts ---------------------
    unsigned full = 0xFFFFFFFFu;
    float v0 = sw, v1 = l1n, v2 = l1d, v3 = l0n, v4 = l0d;
#pragma unroll
    for (int off = 16; off; off >>= 1) {
        v0 += __shfl_down_sync(full, v0, off);
        v1 += __shfl_down_sync(full, v1, off);
        v2 += __shfl_down_sync(full, v2, off);
        v3 += __shfl_down_sync(full, v3, off);
        v4 += __shfl_down_sync(full, v4, off);
    }
    const unsigned pb = __ballot_sync(full, pos);
    const unsigned nb = __ballot_sync(full, neg);

    __shared__ float sh[5][8];
    __shared__ int   sc[2][8];
    const int w = threadIdx.x >> 5, lane = threadIdx.x & 31;
    if (lane == 0) {
        sh[0][w] = v0; sh[1][w] = v1; sh[2][w] = v2; sh[3][w] = v3; sh[4][w] = v4;
        sc[0][w] = __popc(pb); sc[1][w] = __popc(nb);
    }
    __syncthreads();
    if (threadIdx.x == 0) {
        float t0 = 0, t1 = 0, t2 = 0, t3 = 0, t4 = 0;
        int p = 0, nn = 0;
#pragma unroll
        for (int j = 0; j < 8; j++) {
            t0 += sh[0][j]; t1 += sh[1][j]; t2 += sh[2][j]; t3 += sh[3][j]; t4 += sh[4][j];
            p += sc[0][j]; nn += sc[1][j];
        }
        atomicAdd(&g_acc[0], (double)t0);
        atomicAdd(&g_acc[1], (double)t1);
        atomicAdd(&g_acc[2], (double)t2);
        atomicAdd(&g_acc[3], (double)t3);
        atomicAdd(&g_acc[4], (double)t4);
        atomicAdd(&g_npos[b], p);
        atomicAdd(&g_nneg[b], nn);
    }
}

// ---------------- kernel 2: per-batch radix select of k-th smallest --------
__global__ __launch_bounds__(1024) void k_select() {
    const int b = blockIdx.x;
    __shared__ int hist[256];
    __shared__ unsigned s_prefix;
    __shared__ int s_k;

    const int npos = g_npos[b];
    const int nneg = g_nneg[b];
    long long k = 3ll * (long long)npos;
    if ((long long)nneg < k) k = nneg;

    if (npos == 0 || k == 0) {
        if (threadIdx.x == 0) g_thr[b] = 3.402823466e38f;  // FLT_MAX: selects all negs
        return;
    }
    if (threadIdx.x == 0) { s_prefix = 0u; s_k = (int)k; }
    __syncthreads();

    const float* sc = g_masked + (size_t)b * HWSZ;
    for (int shift = 24; shift >= 0; shift -= 8) {
        for (int j = threadIdx.x; j < 256; j += blockDim.x) hist[j] = 0;
        __syncthreads();
        const unsigned pref = s_prefix;
        const unsigned mask = (shift == 24) ? 0u : (0xFFFFFFFFu << (shift + 8));
        for (int j = threadIdx.x; j < HWSZ; j += blockDim.x) {
            const unsigned u = __float_as_uint(sc[j]);   // positive floats: bit order == value order
            if ((u & mask) == pref)
                atomicAdd(&hist[(u >> shift) & 0xFF], 1);
        }
        __syncthreads();
        if (threadIdx.x == 0) {
            int kk = s_k, cum = 0, byte = 255;
            for (int v = 0; v < 256; v++) {
                if (cum + hist[v] >= kk) { byte = v; kk -= cum; break; }
                cum += hist[v];
            }
            s_k = kk;
            s_prefix = pref | ((unsigned)byte << shift);
        }
        __syncthreads();
    }
    if (threadIdx.x == 0) g_thr[b] = __uint_as_float(s_prefix);
}

// ---------------- kernel 3: selected-negative sums --------------------------
__global__ __launch_bounds__(256) void k_pass3() {
    const int i = blockIdx.x * blockDim.x + threadIdx.x;
    const int b = i / HWSZ;
    const float thr = g_thr[b];
    const float msk = g_masked[i];
    const bool sel = (msk <= thr);            // inf > FLT_MAX excludes non-neg in use_all case
    float contrib = sel ? g_clsloss[i] : 0.0f;

    unsigned full = 0xFFFFFFFFu;
#pragma unroll
    for (int off = 16; off; off >>= 1)
        contrib += __shfl_down_sync(full, contrib, off);
    const unsigned sb = __ballot_sync(full, sel);

    __shared__ float shf[8];
    __shared__ int   shi[8];
    const int w = threadIdx.x >> 5, lane = threadIdx.x & 31;
    if (lane == 0) { shf[w] = contrib; shi[w] = __popc(sb); }
    __syncthreads();
    if (threadIdx.x == 0) {
        float t = 0; int cnt = 0;
#pragma unroll
        for (int j = 0; j < 8; j++) { t += shf[j]; cnt += shi[j]; }
        atomicAdd(&g_acc[5], (double)t);
        atomicAdd(&g_nsel, (unsigned long long)cnt);
    }
}

// ---------------- kernel 4: finalize ----------------------------------------
__global__ void k_finalize(float* __restrict__ out) {
    if (threadIdx.x != 0 || blockIdx.x != 0) return;
    long long npos = 0;
#pragma unroll
    for (int b = 0; b < BB; b++) npos += g_npos[b];
    const double nsel = (double)g_nsel;
    const double cls = (g_acc[0] + g_acc[5]) / ((double)npos + nsel);
    double link = 0.0;
    if (npos > 0) {
        const double l1 = (g_acc[2] != 0.0) ? g_acc[1] / g_acc[2] : 0.0;
        const double l0 = (g_acc[4] != 0.0) ? g_acc[3] / g_acc[4] : 0.0;
        link = l1 + l0;
    }
    out[0] = (float)(cls * 2.0);
    out[1] = (float)link;
}

// ---------------- launcher ---------------------------------------------------
extern "C" void kernel_launch(void* const* d_in, const int* in_sizes, int n_in,
                              void* d_out, int out_size) {
    const float* target = (const float*)d_in[0];
    const float* logits = (const float*)d_in[1];
    float* out = (float*)d_out;

    k_zero<<<1, 64>>>();
    k_pass1<<<NPIX / 256, 256>>>(target, logits);
    k_select<<<BB, 1024>>>();
    k_pass3<<<NPIX / 256, 256>>>();
    k_finalize<<<1, 32>>>(out);
}

// round 2
// speedup vs baseline: 1.6535x; 1.6535x over previous
#include <cuda_runtime.h>
#include <cstdint>

#define BB   16
#define HWSZ 65536
#define NPIX (BB * HWSZ)
#define NACC 16

// ---------------- scratch (device globals: allocation is forbidden) --------
__device__ float  g_masked[NPIX];    // neg ? score : +inf
__device__ float  g_clsloss[NPIX];   // per-pixel 2-class CE
__device__ int    g_hist[BB * 4096]; // per-batch histogram of masked bits[31:20]
__device__ double g_acc[5][NACC];    // 0:Sw(ce*w) 1:L1num 2:L1den 3:L0num 4:L0den
__device__ double g_sel_sum;
__device__ unsigned long long g_nsel;
__device__ int    g_npos[BB];
__device__ int    g_nneg[BB];

// ---------------- kernel 0: zero accumulators + histograms -----------------
__global__ void k_zero() {
    const int g = blockIdx.x * 1024 + threadIdx.x;   // 65536 threads
    g_hist[g] = 0;
    if (g < 5 * NACC) ((double*)g_acc)[g] = 0.0;
    if (g < BB) { g_npos[g] = 0; g_nneg[g] = 0; }
    if (g == 0) { g_sel_sum = 0.0; g_nsel = 0ull; }
}

// ---------------- kernel 1: fused pointwise pass ----------------------------
// 4096 blocks x 256 threads; each block = 256 contiguous pixels of one image.
__global__ __launch_bounds__(256) void k_pass1(const float* __restrict__ target,
                                               const float* __restrict__ logits) {
    __shared__ float4 st4[640];          // staged target: 256 pixels * 10 floats
    __shared__ int    shist[4096];
    __shared__ float  shr[5][8];
    __shared__ int    shc[2][8];
    float* st = (float*)st4;

    const int tid = threadIdx.x;
    const int blk = blockIdx.x;
    const int b   = blk >> 8;            // 256 blocks per batch image
    const int i0  = blk << 8;

    // clear shared histogram
#pragma unroll
    for (int j = 0; j < 16; j++) shist[tid + 256 * j] = 0;

    // coalesced float4 staging of target (2560 floats = 640 float4)
    const float4* tg4 = (const float4*)(target + (size_t)i0 * 10);
    st4[tid]       = tg4[tid];
    st4[tid + 256] = tg4[tid + 256];
    if (tid < 128) st4[tid + 512] = tg4[tid + 512];
    __syncthreads();

    const int i  = i0 + tid;
    const int hw = i & (HWSZ - 1);
    const float lab = st[tid * 10 + 0];
    const float wt  = st[tid * 10 + 1];
    const bool pos = lab > 0.0f;
    const bool neg = lab == 0.0f;

    // coalesced channel loads
    const float* lg = logits + (size_t)b * 10 * HWSZ + hw;
    float z[10];
#pragma unroll
    for (int c = 0; c < 10; c++) z[c] = lg[c * HWSZ];

    // 2-class softmax: score + CE
    const float m   = fmaxf(z[0], z[1]);
    const float e0  = __expf(z[0] - m);
    const float e1  = __expf(z[1] - m);
    const float den = e0 + e1;
    const float score  = e0 / den;
    const float cls_ce = -((pos ? z[1] : z[0]) - m - __logf(den));
    const float masked = neg ? score : __uint_as_float(0x7f800000u);

    g_masked[i]  = masked;
    g_clsloss[i] = cls_ce;
    atomicAdd(&shist[__float_as_uint(masked) >> 20], 1);

    const float sw = cls_ce * wt;

    // link CE sums (4 neighbours, 2-class softmax each)
    float l1n = 0.f, l1d = 0.f, l0n = 0.f, l0d = 0.f;
#pragma unroll
    for (int n = 0; n < 4; n++) {
        const float a  = z[2 + n];
        const float c  = z[6 + n];
        const float mm = fmaxf(a, c);
        const float ld = __logf(__expf(a - mm) + __expf(c - mm));
        const int   li = (int)st[tid * 10 + 2 + n];
        const float lw = st[tid * 10 + 6 + n];
        const float ce = -(((li != 0) ? c : a) - mm - ld);
        if (li != 0) { l1n += ce * lw; l1d += lw; }
        else         { l0n += ce * lw; l0d += lw; }
    }

    // block reduction of 5 float sums + 2 counts
    const unsigned full = 0xFFFFFFFFu;
    float v0 = sw, v1 = l1n, v2 = l1d, v3 = l0n, v4 = l0d;
#pragma unroll
    for (int off = 16; off; off >>= 1) {
        v0 += __shfl_down_sync(full, v0, off);
        v1 += __shfl_down_sync(full, v1, off);
        v2 += __shfl_down_sync(full, v2, off);
        v3 += __shfl_down_sync(full, v3, off);
        v4 += __shfl_down_sync(full, v4, off);
    }
    const unsigned pb = __ballot_sync(full, pos);
    const unsigned nb = __ballot_sync(full, neg);
    const int w = tid >> 5, lane = tid & 31;
    if (lane == 0) {
        shr[0][w] = v0; shr[1][w] = v1; shr[2][w] = v2; shr[3][w] = v3; shr[4][w] = v4;
        shc[0][w] = __popc(pb); shc[1][w] = __popc(nb);
    }
    __syncthreads();   // covers both reduction smem and shist atomics

    if (tid == 0) {
        float t0 = 0, t1 = 0, t2 = 0, t3 = 0, t4 = 0;
        int p = 0, nn = 0;
#pragma unroll
        for (int j = 0; j < 8; j++) {
            t0 += shr[0][j]; t1 += shr[1][j]; t2 += shr[2][j]; t3 += shr[3][j]; t4 += shr[4][j];
            p += shc[0][j];  nn += shc[1][j];
        }
        const int slot = blk & (NACC - 1);
        atomicAdd(&g_acc[0][slot], (double)t0);
        atomicAdd(&g_acc[1][slot], (double)t1);
        atomicAdd(&g_acc[2][slot], (double)t2);
        atomicAdd(&g_acc[3][slot], (double)t3);
        atomicAdd(&g_acc[4][slot], (double)t4);
        atomicAdd(&g_npos[b], p);
        atomicAdd(&g_nneg[b], nn);
    }

    // merge shared histogram into per-batch global histogram (sparse)
#pragma unroll
    for (int j = 0; j < 16; j++) {
        const int h = shist[tid + 256 * j];
        if (h) atomicAdd(&g_hist[(b << 12) + tid + 256 * j], h);
    }
}

// ---------------- 12-bit digit resolve via parallel block scan --------------
// hist: 4096 bins in shared; s_k holds k on entry, k-remainder on exit;
// s_d gets the selected digit. Block of 1024 threads, uniform call.
__device__ __forceinline__ void resolve12(int* hist, int* scan, int* s_d, int* s_k) {
    const int tid = threadIdx.x;
    const int kcur = *s_k;
    const int part = hist[tid * 4] + hist[tid * 4 + 1] + hist[tid * 4 + 2] + hist[tid * 4 + 3];
    int v = part;
    scan[tid] = v;
    __syncthreads();
#pragma unroll
    for (int off = 1; off < 1024; off <<= 1) {
        const int add = (tid >= off) ? scan[tid - off] : 0;
        __syncthreads();
        v += add;
        scan[tid] = v;
        __syncthreads();
    }
    if (v >= kcur && v - part < kcur) {    // unique owner thread
        int cum = v - part;
#pragma unroll
        for (int ii = 0; ii < 4; ii++) {
            const int h = hist[tid * 4 + ii];
            if (cum + h >= kcur) { *s_d = tid * 4 + ii; *s_k = kcur - cum; break; }
            cum += h;
        }
    }
    __syncthreads();
}

// ---------------- kernel 2: radix-select threshold + selected sums ----------
__global__ __launch_bounds__(1024) void k_select() {
    const int b   = blockIdx.x;
    const int tid = threadIdx.x;
    __shared__ int   hist[4096];
    __shared__ int   scan[1024];
    __shared__ int   s_d, s_k;
    __shared__ float s_thr;
    __shared__ float swsum[32];
    __shared__ int   swcnt[32];

    const int npos = g_npos[b];
    const int nneg = g_nneg[b];
    long long kk = 3ll * (long long)npos;
    if ((long long)nneg < kk) kk = nneg;
    const bool use_all = (npos == 0) || (kk == 0);

    const float* sc = g_masked  + ((size_t)b << 16);
    const float* cl = g_clsloss + ((size_t)b << 16);

    if (!use_all) {
        // digit 0 (bits[31:20]) from precomputed histogram — no data pass
        const int* gh = g_hist + (b << 12);
#pragma unroll
        for (int j = 0; j < 4; j++) hist[tid + 1024 * j] = gh[tid + 1024 * j];
        if (tid == 0) s_k = (int)kk;
        __syncthreads();
        resolve12(hist, scan, &s_d, &s_k);
        const unsigned d0 = (unsigned)s_d;

        // digit 1 (bits[19:8])
#pragma unroll
        for (int j = 0; j < 4; j++) hist[tid + 1024 * j] = 0;
        __syncthreads();
        for (int j = tid; j < HWSZ; j += 1024) {
            const unsigned u = __float_as_uint(sc[j]);
            if ((u >> 20) == d0) atomicAdd(&hist[(u >> 8) & 0xFFFu], 1);
        }
        __syncthreads();
        resolve12(hist, scan, &s_d, &s_k);
        const unsigned pre24 = (d0 << 12) | (unsigned)s_d;

        // digit 2 (bits[7:0])
        if (tid < 256) hist[tid] = 0;
        __syncthreads();
        for (int j = tid; j < HWSZ; j += 1024) {
            const unsigned u = __float_as_uint(sc[j]);
            if ((u >> 8) == pre24) atomicAdd(&hist[u & 0xFFu], 1);
        }
        __syncthreads();
        if (tid == 0) {
            int kcur = s_k, cum = 0; unsigned d2 = 255;
            for (int v2 = 0; v2 < 256; v2++) {
                const int h = hist[v2];
                if (cum + h >= kcur) { d2 = (unsigned)v2; break; }
                cum += h;
            }
            s_thr = __uint_as_float((pre24 << 8) | d2);
        }
        __syncthreads();
    } else {
        if (tid == 0) s_thr = 3.402823466e38f;   // FLT_MAX < +inf: selects all negs
        __syncthreads();
    }

    // fused selected-negative sum pass (replaces old k_pass3)
    const float thr = s_thr;
    float sum = 0.f; int cnt = 0;
    for (int j = tid; j < HWSZ; j += 1024) {
        const float m = sc[j];
        if (m <= thr) { sum += cl[j]; cnt++; }
    }
#pragma unroll
    for (int off = 16; off; off >>= 1) {
        sum += __shfl_down_sync(0xFFFFFFFFu, sum, off);
        cnt += __shfl_down_sync(0xFFFFFFFFu, cnt, off);
    }
    const int w = tid >> 5, lane = tid & 31;
    if (lane == 0) { swsum[w] = sum; swcnt[w] = cnt; }
    __syncthreads();
    if (tid == 0) {
        float t = 0; int c = 0;
#pragma unroll
        for (int j = 0; j < 32; j++) { t += swsum[j]; c += swcnt[j]; }
        atomicAdd(&g_sel_sum, (double)t);
        atomicAdd(&g_nsel, (unsigned long long)c);
    }
}

// ---------------- kernel 3: finalize -----------------------------------------
__global__ void k_finalize(float* __restrict__ out) {
    if (threadIdx.x != 0 || blockIdx.x != 0) return;
    double a[5] = {0, 0, 0, 0, 0};
#pragma unroll
    for (int r = 0; r < 5; r++)
        for (int s = 0; s < NACC; s++) a[r] += g_acc[r][s];
    long long npos = 0;
#pragma unroll
    for (int b = 0; b < BB; b++) npos += g_npos[b];
    const double cls = (a[0] + g_sel_sum) / ((double)npos + (double)g_nsel);
    double link = 0.0;
    if (npos > 0) {
        const double l1 = (a[2] != 0.0) ? a[1] / a[2] : 0.0;
        const double l0 = (a[4] != 0.0) ? a[3] / a[4] : 0.0;
        link = l1 + l0;
    }
    out[0] = (float)(cls * 2.0);
    out[1] = (float)link;
}

// ---------------- launcher ----------------------------------------------------
extern "C" void kernel_launch(void* const* d_in, const int* in_sizes, int n_in,
                              void* d_out, int out_size) {
    const float* target = (const float*)d_in[0];
    const float* logits = (const float*)d_in[1];
    float* out = (float*)d_out;

    k_zero<<<64, 1024>>>();
    k_pass1<<<NPIX / 256, 256>>>(target, logits);
    k_select<<<BB, 1024>>>();
    k_finalize<<<1, 32>>>(out);
}

// round 3
// speedup vs baseline: 1.7610x; 1.0650x over previous
#include <cuda_runtime.h>
#include <cstdint>

#define BB    16
#define HWSZ  65536
#define NPIX  (BB * HWSZ)
#define NACC  16
#define PXB   512                 // pixels per pass1 block
#define P1BLK (NPIX / PXB)        // 2048

// ---------------- scratch (device globals zero-initialized at load) --------
__device__ float  g_masked[NPIX];    // neg ? score : +inf
__device__ float  g_clsloss[NPIX];   // per-pixel 2-class CE
__device__ int    g_hist[BB * 4096]; // per-batch histogram of masked bits[31:20]
__device__ double g_acc[5][NACC];    // 0:Sw(ce*w) 1:L1num 2:L1den 3:L0num 4:L0den
__device__ double g_sel_sum;
__device__ unsigned long long g_nsel;
__device__ int    g_npos[BB];
__device__ int    g_nneg[BB];
__device__ unsigned g_done;

__device__ __forceinline__ float comp2(const float2 v, int q) { return q ? v.y : v.x; }

// ---------------- kernel 1: fused pointwise pass ----------------------------
// 2048 blocks x 256 threads; block = 512 contiguous pixels of one image.
__global__ __launch_bounds__(256) void k_pass1(const float* __restrict__ target,
                                               const float* __restrict__ logits) {
    __shared__ float st[10 * PXB];       // SoA staged target: 20 KB
    __shared__ int   shist[4096];
    __shared__ float shr[5][8];
    __shared__ int   shc[2][8];

    const int tid = threadIdx.x;
    const int blk = blockIdx.x;
    const int b   = blk >> 7;            // 128 blocks per batch image
    const int i0  = blk * PXB;
    const int hw0 = (blk & 127) * PXB;

#pragma unroll
    for (int j = 0; j < 16; j++) shist[tid + 256 * j] = 0;

    // stage target AoS->SoA: 512 px * 10 floats = 1280 float4, coalesced loads
    const float4* tg4 = (const float4*)(target + (size_t)i0 * 10);
#pragma unroll
    for (int jj = 0; jj < 5; jj++) {
        const int j = tid + 256 * jj;
        const float4 v = tg4[j];
        const int f0 = 4 * j;
        {
            int f = f0 + 0, p = f / 10; st[(f - p * 10) * PXB + p] = v.x;
        }
        {
            int f = f0 + 1, p = f / 10; st[(f - p * 10) * PXB + p] = v.y;
        }
        {
            int f = f0 + 2, p = f / 10; st[(f - p * 10) * PXB + p] = v.z;
        }
        {
            int f = f0 + 3, p = f / 10; st[(f - p * 10) * PXB + p] = v.w;
        }
    }
    __syncthreads();

    // coalesced float2 loads: 2 pixels per thread
    const float2* lg2 = (const float2*)(logits + (size_t)b * 10 * HWSZ + hw0);
    float2 z2[10];
#pragma unroll
    for (int c = 0; c < 10; c++) z2[c] = lg2[c * (HWSZ / 2) + tid];

    const float2 lab2 = ((const float2*)st)[0 * (PXB / 2) + tid];
    const float2 wt2  = ((const float2*)st)[1 * (PXB / 2) + tid];

    float sw = 0.f, l1n = 0.f, l1d = 0.f, l0n = 0.f, l0d = 0.f;
    int cpos = 0, cneg = 0;
    float2 out_m, out_c;

#pragma unroll
    for (int q = 0; q < 2; q++) {
        const float lab = comp2(lab2, q);
        const float wt  = comp2(wt2, q);
        const bool pos = lab > 0.0f;
        const bool neg = lab == 0.0f;
        cpos += pos; cneg += neg;

        const float z0 = comp2(z2[0], q);
        const float z1 = comp2(z2[1], q);
        const float d  = z1 - z0;
        const float e  = __expf(-fabsf(d));
        const float lp = __logf(1.0f + e);
        const float m  = fmaxf(z0, z1);
        const float ce = lp + m - (pos ? z1 : z0);
        const float r  = __fdividef(1.0f, 1.0f + e);
        const float score  = (d > 0.0f) ? e * r : r;     // p0 = sigmoid(z0-z1)
        const float masked = neg ? score : __uint_as_float(0x7f800000u);

        if (q) { out_m.y = masked; out_c.y = ce; }
        else   { out_m.x = masked; out_c.x = ce; }
        atomicAdd(&shist[__float_as_uint(masked) >> 20], 1);
        sw += ce * wt;

#pragma unroll
        for (int n = 0; n < 4; n++) {
            const float a  = comp2(z2[2 + n], q);
            const float c  = comp2(z2[6 + n], q);
            const float dd = c - a;
            const float ee = __expf(-fabsf(dd));
            const float ld = __logf(1.0f + ee);
            const float mm = fmaxf(a, c);
            const bool  li = comp2(((const float2*)st)[(2 + n) * (PXB / 2) + tid], q) != 0.0f;
            const float lw = comp2(((const float2*)st)[(6 + n) * (PXB / 2) + tid], q);
            const float lce = ld + mm - (li ? c : a);
            if (li) { l1n += lce * lw; l1d += lw; }
            else    { l0n += lce * lw; l0d += lw; }
        }
    }

    ((float2*)(g_masked  + i0))[tid] = out_m;
    ((float2*)(g_clsloss + i0))[tid] = out_c;

    // -------- block reduction: 5 floats + 2 counts --------------------------
    const unsigned full = 0xFFFFFFFFu;
    float v0 = sw, v1 = l1n, v2 = l1d, v3 = l0n, v4 = l0d;
    int ip = cpos, in_ = cneg;
#pragma unroll
    for (int off = 16; off; off >>= 1) {
        v0 += __shfl_down_sync(full, v0, off);
        v1 += __shfl_down_sync(full, v1, off);
        v2 += __shfl_down_sync(full, v2, off);
        v3 += __shfl_down_sync(full, v3, off);
        v4 += __shfl_down_sync(full, v4, off);
        ip += __shfl_down_sync(full, ip, off);
        in_ += __shfl_down_sync(full, in_, off);
    }
    const int w = tid >> 5, lane = tid & 31;
    if (lane == 0) {
        shr[0][w] = v0; shr[1][w] = v1; shr[2][w] = v2; shr[3][w] = v3; shr[4][w] = v4;
        shc[0][w] = ip; shc[1][w] = in_;
    }
    __syncthreads();

    if (tid == 0) {
        float t0 = 0, t1 = 0, t2 = 0, t3 = 0, t4 = 0;
        int p = 0, nn = 0;
#pragma unroll
        for (int j = 0; j < 8; j++) {
            t0 += shr[0][j]; t1 += shr[1][j]; t2 += shr[2][j]; t3 += shr[3][j]; t4 += shr[4][j];
            p += shc[0][j];  nn += shc[1][j];
        }
        const int slot = blk & (NACC - 1);
        atomicAdd(&g_acc[0][slot], (double)t0);
        atomicAdd(&g_acc[1][slot], (double)t1);
        atomicAdd(&g_acc[2][slot], (double)t2);
        atomicAdd(&g_acc[3][slot], (double)t3);
        atomicAdd(&g_acc[4][slot], (double)t4);
        atomicAdd(&g_npos[b], p);
        atomicAdd(&g_nneg[b], nn);
    }

    // merge shared histogram into per-batch global histogram (sparse)
#pragma unroll
    for (int j = 0; j < 16; j++) {
        const int h = shist[tid + 256 * j];
        if (h) atomicAdd(&g_hist[(b << 12) + tid + 256 * j], h);
    }
}

// ---------------- 12-bit digit resolve, warp-shfl scan ----------------------
__device__ __forceinline__ void resolve12(const int* hist, int* warpsum,
                                          volatile int* s_d, volatile int* s_k) {
    const int tid = threadIdx.x;
    const int lane = tid & 31, wid = tid >> 5;
    const unsigned full = 0xFFFFFFFFu;
    const int kcur = *s_k;
    const int h0 = hist[4 * tid], h1 = hist[4 * tid + 1],
              h2 = hist[4 * tid + 2], h3 = hist[4 * tid + 3];
    const int part = h0 + h1 + h2 + h3;
    int v = part;
#pragma unroll
    for (int off = 1; off < 32; off <<= 1) {
        const int n = __shfl_up_sync(full, v, off);
        if (lane >= off) v += n;
    }
    if (lane == 31) warpsum[wid] = v;
    __syncthreads();
    if (wid == 0) {
        int s = warpsum[lane];
#pragma unroll
        for (int off = 1; off < 32; off <<= 1) {
            const int n = __shfl_up_sync(full, s, off);
            if (lane >= off) s += n;
        }
        warpsum[lane] = s;
    }
    __syncthreads();
    const int incl = v + (wid ? warpsum[wid - 1] : 0);
    const int excl = incl - part;
    if (incl >= kcur && excl < kcur) {       // unique owner
        int cum = excl, dg = 4 * tid, kk = kcur;
        if (cum + h0 >= kk) { *s_d = dg; *s_k = kk - cum; }
        else if (cum + h0 + h1 >= kk) { *s_d = dg + 1; *s_k = kk - cum - h0; }
        else if (cum + h0 + h1 + h2 >= kk) { *s_d = dg + 2; *s_k = kk - cum - h0 - h1; }
        else { *s_d = dg + 3; *s_k = kk - cum - h0 - h1 - h2; }
    }
    __syncthreads();
}

// ---------------- kernel 2: radix-select + selected sums + fused finalize ---
__global__ __launch_bounds__(1024) void k_select(float* __restrict__ out) {
    const int b   = blockIdx.x;
    const int tid = threadIdx.x;
    __shared__ int   hist[4096];
    __shared__ int   warpsum[32];
    __shared__ int   s_d, s_k;
    __shared__ float s_thr;
    __shared__ float swsum[32];
    __shared__ int   swcnt[32];
    __shared__ int   s_last;

    const int npos = g_npos[b];
    const int nneg = g_nneg[b];
    long long kk = 3ll * (long long)npos;
    if ((long long)nneg < kk) kk = nneg;
    const bool use_all = (npos == 0) || (kk == 0);

    const float* sc = g_masked  + ((size_t)b << 16);
    const float* cl = g_clsloss + ((size_t)b << 16);
    int* gh = g_hist + (b << 12);

    if (!use_all) {
        // digit 0 (bits[31:20]) from precomputed histogram — zero data passes
#pragma unroll
        for (int j = 0; j < 4; j++) hist[tid + 1024 * j] = gh[tid + 1024 * j];
#pragma unroll
        for (int j = 0; j < 4; j++) gh[tid + 1024 * j] = 0;   // self-clean
        if (tid == 0) s_k = (int)kk;
        __syncthreads();
        resolve12(hist, warpsum, &s_d, &s_k);
        const unsigned d0 = (unsigned)s_d;

        // digit 1 (bits[19:8])
#pragma unroll
        for (int j = 0; j < 4; j++) hist[tid + 1024 * j] = 0;
        __syncthreads();
        const float4* sc4 = (const float4*)sc;
        for (int j = tid; j < HWSZ / 4; j += 1024) {
            const float4 v = sc4[j];
            unsigned u;
            u = __float_as_uint(v.x); if ((u >> 20) == d0) atomicAdd(&hist[(u >> 8) & 0xFFFu], 1);
            u = __float_as_uint(v.y); if ((u >> 20) == d0) atomicAdd(&hist[(u >> 8) & 0xFFFu], 1);
            u = __float_as_uint(v.z); if ((u >> 20) == d0) atomicAdd(&hist[(u >> 8) & 0xFFFu], 1);
            u = __float_as_uint(v.w); if ((u >> 20) == d0) atomicAdd(&hist[(u >> 8) & 0xFFFu], 1);
        }
        __syncthreads();
        resolve12(hist, warpsum, &s_d, &s_k);
        const unsigned pre24 = (d0 << 12) | (unsigned)s_d;

        // digit 2 (bits[7:0])
        if (tid < 256) hist[tid] = 0;
        __syncthreads();
        for (int j = tid; j < HWSZ / 4; j += 1024) {
            const float4 v = sc4[j];
            unsigned u;
            u = __float_as_uint(v.x); if ((u >> 8) == pre24) atomicAdd(&hist[u & 0xFFu], 1);
            u = __float_as_uint(v.y); if ((u >> 8) == pre24) atomicAdd(&hist[u & 0xFFu], 1);
            u = __float_as_uint(v.z); if ((u >> 8) == pre24) atomicAdd(&hist[u & 0xFFu], 1);
            u = __float_as_uint(v.w); if ((u >> 8) == pre24) atomicAdd(&hist[u & 0xFFu], 1);
        }
        __syncthreads();
        if (tid == 0) {
            int kcur = s_k, cum = 0; unsigned d2 = 255;
            for (int v2 = 0; v2 < 256; v2++) {
                const int h = hist[v2];
                if (cum + h >= kcur) { d2 = (unsigned)v2; break; }
                cum += h;
            }
            s_thr = __uint_as_float((pre24 << 8) | d2);
        }
        __syncthreads();
    } else {
#pragma unroll
        for (int j = 0; j < 4; j++) gh[tid + 1024 * j] = 0;   // self-clean
        if (tid == 0) s_thr = 3.402823466e38f;   // FLT_MAX < +inf: all negs
        __syncthreads();
    }

    // fused selected-negative sums
    const float thr = s_thr;
    float sum = 0.f; int cnt = 0;
    const float4* sc4 = (const float4*)sc;
    const float4* cl4 = (const float4*)cl;
    for (int j = tid; j < HWSZ / 4; j += 1024) {
        const float4 m4 = sc4[j];
        const float4 c4 = cl4[j];
        if (m4.x <= thr) { sum += c4.x; cnt++; }
        if (m4.y <= thr) { sum += c4.y; cnt++; }
        if (m4.z <= thr) { sum += c4.z; cnt++; }
        if (m4.w <= thr) { sum += c4.w; cnt++; }
    }
    const unsigned full = 0xFFFFFFFFu;
#pragma unroll
    for (int off = 16; off; off >>= 1) {
        sum += __shfl_down_sync(full, sum, off);
        cnt += __shfl_down_sync(full, cnt, off);
    }
    const int w = tid >> 5, lane = tid & 31;
    if (lane == 0) { swsum[w] = sum; swcnt[w] = cnt; }
    __syncthreads();
    if (tid == 0) {
        float t = 0; int c = 0;
#pragma unroll
        for (int j = 0; j < 32; j++) { t += swsum[j]; c += swcnt[j]; }
        atomicAdd(&g_sel_sum, (double)t);
        atomicAdd(&g_nsel, (unsigned long long)c);
        __threadfence();
        const unsigned prev = atomicAdd(&g_done, 1u);
        s_last = (prev == BB - 1);
    }
    __syncthreads();

    // -------- last block: fused finalize + global state reset ---------------
    if (s_last) {
        __threadfence();
        if (tid < 32) {
            double a[5];
#pragma unroll
            for (int r = 0; r < 5; r++) {
                double v = (lane < NACC) ? g_acc[r][lane] : 0.0;
#pragma unroll
                for (int off = 16; off; off >>= 1) v += __shfl_down_sync(full, v, off);
                a[r] = v;
            }
            int np = (lane < BB) ? g_npos[lane] : 0;
#pragma unroll
            for (int off = 16; off; off >>= 1) np += __shfl_down_sync(full, np, off);
            if (lane == 0) {
                const double cls = (a[0] + g_sel_sum) / ((double)np + (double)g_nsel);
                double link = 0.0;
                if (np > 0) {
                    const double l1 = (a[2] != 0.0) ? a[1] / a[2] : 0.0;
                    const double l0 = (a[4] != 0.0) ? a[3] / a[4] : 0.0;
                    link = l1 + l0;
                }
                out[0] = (float)(cls * 2.0);
                out[1] = (float)link;
            }
        }
        __syncthreads();
        // reset for next graph replay
        if (tid < 5 * NACC) ((double*)g_acc)[tid] = 0.0;
        if (tid >= 128 && tid < 128 + BB) { g_npos[tid - 128] = 0; g_nneg[tid - 128] = 0; }
        if (tid == 256) { g_sel_sum = 0.0; g_nsel = 0ull; }
        if (tid == 288) g_done = 0u;
    }
}

// ---------------- launcher ----------------------------------------------------
extern "C" void kernel_launch(void* const* d_in, const int* in_sizes, int n_in,
                              void* d_out, int out_size) {
    const float* target = (const float*)d_in[0];
    const float* logits = (const float*)d_in[1];
    float* out = (float*)d_out;

    k_pass1<<<P1BLK, 256>>>(target, logits);
    k_select<<<BB, 1024>>>(out);
}

// round 4
// speedup vs baseline: 3.5049x; 1.9903x over previous
#include <cuda_runtime.h>
#include <cstdint>

#define BB    16
#define HWSZ  65536
#define NPIX  (BB * HWSZ)
#define NACC  16
#define PXB   512                 // pixels per block
#define P1BLK (NPIX / PXB)        // 2048 blocks

// ---------------- device-global scratch (zero-initialized at load) ---------
__device__ float  g_masked[NPIX];    // neg ? score : +inf  (slow path only)
__device__ float  g_clsloss[NPIX];   // per-pixel 2-class CE (slow path only)
__device__ double g_acc[5][NACC];    // 0:Sw(ce*w) 1:L1num 2:L1den 3:L0num 4:L0den
__device__ double g_negsum[BB];      // per-batch sum of ce over negatives
__device__ int    g_npos[BB];
__device__ int    g_nneg[BB];
__device__ unsigned g_done;

__device__ __forceinline__ float comp2(const float2 v, int q) { return q ? v.y : v.x; }

// ---------------- single fused kernel ---------------------------------------
__global__ __launch_bounds__(256) void k_fused(const float* __restrict__ target,
                                               const float* __restrict__ logits,
                                               float* __restrict__ out) {
    __shared__ float st[10 * PXB];       // SoA staged target: 20 KB
    __shared__ float shr[6][8];
    __shared__ int   shc[2][8];
    __shared__ int   s_last;

    const int tid = threadIdx.x;
    const int blk = blockIdx.x;
    const int b   = blk >> 7;            // 128 blocks per batch image
    const int i0  = blk * PXB;
    const int hw0 = (blk & 127) * PXB;
    const int w = tid >> 5, lane = tid & 31;
    const unsigned full = 0xFFFFFFFFu;

    // stage target AoS->SoA: 512 px * 10 floats = 1280 float4, coalesced
    const float4* tg4 = (const float4*)(target + (size_t)i0 * 10);
#pragma unroll
    for (int jj = 0; jj < 5; jj++) {
        const int j = tid + 256 * jj;
        const float4 v = tg4[j];
        const int f0 = 4 * j;
        { int f = f0 + 0, p = f / 10; st[(f - p * 10) * PXB + p] = v.x; }
        { int f = f0 + 1, p = f / 10; st[(f - p * 10) * PXB + p] = v.y; }
        { int f = f0 + 2, p = f / 10; st[(f - p * 10) * PXB + p] = v.z; }
        { int f = f0 + 3, p = f / 10; st[(f - p * 10) * PXB + p] = v.w; }
    }
    __syncthreads();

    // coalesced float2 channel loads: 2 pixels per thread
    const float2* lg2 = (const float2*)(logits + (size_t)b * 10 * HWSZ + hw0);
    float2 z2[10];
#pragma unroll
    for (int c = 0; c < 10; c++) z2[c] = lg2[c * (HWSZ / 2) + tid];

    const float2 lab2 = ((const float2*)st)[0 * (PXB / 2) + tid];
    const float2 wt2  = ((const float2*)st)[1 * (PXB / 2) + tid];

    float sw = 0.f, l1n = 0.f, l1d = 0.f, l0n = 0.f, l0d = 0.f, ns = 0.f;
    int cpos = 0, cneg = 0;
    float2 out_m, out_c;

#pragma unroll
    for (int q = 0; q < 2; q++) {
        const float lab = comp2(lab2, q);
        const float wt  = comp2(wt2, q);
        const bool pos = lab > 0.0f;
        const bool neg = lab == 0.0f;
        cpos += pos; cneg += neg;

        const float z0 = comp2(z2[0], q);
        const float z1 = comp2(z2[1], q);
        const float d  = z1 - z0;
        const float e  = __expf(-fabsf(d));
        const float lp = __logf(1.0f + e);
        const float m  = fmaxf(z0, z1);
        const float ce = lp + m - (pos ? z1 : z0);
        const float r  = __fdividef(1.0f, 1.0f + e);
        const float score  = (d > 0.0f) ? e * r : r;     // p0 = sigmoid(z0-z1)
        const float masked = neg ? score : __uint_as_float(0x7f800000u);

        if (q) { out_m.y = masked; out_c.y = ce; }
        else   { out_m.x = masked; out_c.x = ce; }
        sw += ce * wt;
        if (neg) ns += ce;

#pragma unroll
        for (int n = 0; n < 4; n++) {
            const float a  = comp2(z2[2 + n], q);
            const float c  = comp2(z2[6 + n], q);
            const float dd = c - a;
            const float ee = __expf(-fabsf(dd));
            const float ld = __logf(1.0f + ee);
            const float mm = fmaxf(a, c);
            const bool  li = comp2(((const float2*)st)[(2 + n) * (PXB / 2) + tid], q) != 0.0f;
            const float lw = comp2(((const float2*)st)[(6 + n) * (PXB / 2) + tid], q);
            const float lce = ld + mm - (li ? c : a);
            if (li) { l1n += lce * lw; l1d += lw; }
            else    { l0n += lce * lw; l0d += lw; }
        }
    }

    ((float2*)(g_masked  + i0))[tid] = out_m;
    ((float2*)(g_clsloss + i0))[tid] = out_c;

    // -------- block reduction: 6 floats + 2 counts --------------------------
    float v0 = sw, v1 = l1n, v2 = l1d, v3 = l0n, v4 = l0d, v5 = ns;
    int ip = cpos, in_ = cneg;
#pragma unroll
    for (int off = 16; off; off >>= 1) {
        v0 += __shfl_down_sync(full, v0, off);
        v1 += __shfl_down_sync(full, v1, off);
        v2 += __shfl_down_sync(full, v2, off);
        v3 += __shfl_down_sync(full, v3, off);
        v4 += __shfl_down_sync(full, v4, off);
        v5 += __shfl_down_sync(full, v5, off);
        ip += __shfl_down_sync(full, ip, off);
        in_ += __shfl_down_sync(full, in_, off);
    }
    if (lane == 0) {
        shr[0][w] = v0; shr[1][w] = v1; shr[2][w] = v2;
        shr[3][w] = v3; shr[4][w] = v4; shr[5][w] = v5;
        shc[0][w] = ip; shc[1][w] = in_;
    }
    __syncthreads();

    if (tid == 0) {
        float t0 = 0, t1 = 0, t2 = 0, t3 = 0, t4 = 0, t5 = 0;
        int p = 0, nn = 0;
#pragma unroll
        for (int j = 0; j < 8; j++) {
            t0 += shr[0][j]; t1 += shr[1][j]; t2 += shr[2][j];
            t3 += shr[3][j]; t4 += shr[4][j]; t5 += shr[5][j];
            p += shc[0][j];  nn += shc[1][j];
        }
        const int slot = blk & (NACC - 1);
        atomicAdd(&g_acc[0][slot], (double)t0);
        atomicAdd(&g_acc[1][slot], (double)t1);
        atomicAdd(&g_acc[2][slot], (double)t2);
        atomicAdd(&g_acc[3][slot], (double)t3);
        atomicAdd(&g_acc[4][slot], (double)t4);
        atomicAdd(&g_negsum[b], (double)t5);
        atomicAdd(&g_npos[b], p);
        atomicAdd(&g_nneg[b], nn);
        __threadfence();
        const unsigned prev = atomicAdd(&g_done, 1u);
        s_last = (prev == P1BLK - 1);
    }
    __syncthreads();
    if (!s_last) return;

    // =================== tail: last block only ===============================
    __threadfence();
    __shared__ double   sels[BB];
    __shared__ long long nsels[BB];
    __shared__ unsigned s_slowmask;
    __shared__ int      hist[256];
    __shared__ unsigned s_pref;
    __shared__ int      s_k;
    __shared__ float    ssum[8];
    __shared__ int      scnt[8];

    if (tid == 0) s_slowmask = 0u;
    __syncthreads();

    if (tid < BB) {
        const int np = __ldcg(&g_npos[tid]);
        const int nn = __ldcg(&g_nneg[tid]);
        long long k = 3ll * np; if ((long long)nn < k) k = nn;
        if (np == 0 || k == 0 || k == (long long)nn) {
            // fast path: selected == all negatives (threshold = max neg score,
            // or use_all case) -> sum precomputed in pass1
            sels[tid]  = __ldcg(&g_negsum[tid]);
            nsels[tid] = nn;
        } else {
            sels[tid] = 0.0; nsels[tid] = 0;
            atomicOr(&s_slowmask, 1u << tid);
        }
    }
    __syncthreads();

    // slow path (generic correctness; 0 < k < nneg). Rare/never for this data.
    unsigned slow = s_slowmask;
    while (slow) {
        const int bb = __ffs(slow) - 1;
        slow &= slow - 1;
        const int np = __ldcg(&g_npos[bb]);
        const int nn = __ldcg(&g_nneg[bb]);
        long long k = 3ll * np; if ((long long)nn < k) k = nn;
        const float* sc = g_masked  + ((size_t)bb << 16);
        const float* cl = g_clsloss + ((size_t)bb << 16);

        if (tid == 0) { s_pref = 0u; s_k = (int)k; }
        __syncthreads();
        for (int shift = 24; shift >= 0; shift -= 8) {
            hist[tid] = 0;        // blockDim == 256
            __syncthreads();
            const unsigned pref = s_pref;
            const unsigned mask = (shift == 24) ? 0u : (0xFFFFFFFFu << (shift + 8));
            for (int j = tid; j < HWSZ; j += 256) {
                const unsigned u = __float_as_uint(__ldcg(&sc[j]));
                if ((u & mask) == pref) atomicAdd(&hist[(u >> shift) & 0xFFu], 1);
            }
            __syncthreads();
            if (tid == 0) {
                int kk = s_k, cum = 0; unsigned dd = 255;
                for (int v = 0; v < 256; v++) {
                    const int h = hist[v];
                    if (cum + h >= kk) { dd = (unsigned)v; s_k = kk - cum; break; }
                    cum += h;
                }
                s_pref = pref | (dd << shift);
            }
            __syncthreads();
        }
        const float thr = __uint_as_float(s_pref);
        float sum = 0.f; int cnt = 0;
        for (int j = tid; j < HWSZ; j += 256) {
            const float m = __ldcg(&sc[j]);
            if (m <= thr) { sum += __ldcg(&cl[j]); cnt++; }
        }
#pragma unroll
        for (int off = 16; off; off >>= 1) {
            sum += __shfl_down_sync(full, sum, off);
            cnt += __shfl_down_sync(full, cnt, off);
        }
        if (lane == 0) { ssum[w] = sum; scnt[w] = cnt; }
        __syncthreads();
        if (tid == 0) {
            float t = 0; int c = 0;
#pragma unroll
            for (int j = 0; j < 8; j++) { t += ssum[j]; c += scnt[j]; }
            sels[bb] = (double)t; nsels[bb] = c;
        }
        __syncthreads();
    }

    // -------- finalize (warp 0) ---------------------------------------------
    if (tid < 32) {
        double a[5];
#pragma unroll
        for (int r = 0; r < 5; r++) {
            double v = (lane < NACC) ? __ldcg(&g_acc[r][lane]) : 0.0;
#pragma unroll
            for (int off = 16; off; off >>= 1) v += __shfl_down_sync(full, v, off);
            a[r] = v;
        }
        int np = (lane < BB) ? __ldcg(&g_npos[lane]) : 0;
        double ss = (lane < BB) ? sels[lane] : 0.0;
        long long nsl = (lane < BB) ? nsels[lane] : 0ll;
#pragma unroll
        for (int off = 16; off; off >>= 1) {
            np  += __shfl_down_sync(full, np, off);
            ss  += __shfl_down_sync(full, ss, off);
            nsl += __shfl_down_sync(full, nsl, off);
        }
        if (lane == 0) {
            const double cls = (a[0] + ss) / ((double)np + (double)nsl);
            double link = 0.0;
            if (np > 0) {
                const double l1 = (a[2] != 0.0) ? a[1] / a[2] : 0.0;
                const double l0 = (a[4] != 0.0) ? a[3] / a[4] : 0.0;
                link = l1 + l0;
            }
            out[0] = (float)(cls * 2.0);
            out[1] = (float)link;
        }
    }
    __syncthreads();

    // -------- reset global state for next graph replay ----------------------
    if (tid < 5 * NACC) ((double*)g_acc)[tid] = 0.0;
    if (tid >= 96 && tid < 96 + BB) g_negsum[tid - 96] = 0.0;
    if (tid >= 128 && tid < 128 + BB) { g_npos[tid - 128] = 0; g_nneg[tid - 128] = 0; }
    if (tid == 192) g_done = 0u;
}

// ---------------- launcher ----------------------------------------------------
extern "C" void kernel_launch(void* const* d_in, const int* in_sizes, int n_in,
                              void* d_out, int out_size) {
    const float* target = (const float*)d_in[0];
    const float* logits = (const float*)d_in[1];
    float* out = (float*)d_out;

    k_fused<<<P1BLK, 256>>>(target, logits, out);
}

// round 5
// speedup vs baseline: 3.8415x; 1.0960x over previous
#include <cuda_runtime.h>
#include <cstdint>

#define BB    16
#define HWSZ  65536
#define NPIX  (BB * HWSZ)
#define NACC  16
#define PXB   512                  // pixels per block
#define NBLK  (NPIX / PXB)         // 2048 blocks
#define SP    520                  // padded SoA stride (floats)

// ---------------- device-global scratch (zero-initialized at load) ---------
__device__ float  g_masked[NPIX];    // slow path only
__device__ float  g_clsloss[NPIX];   // slow path only
__device__ double g_acc[5][NACC];    // 0:Sw(ce*w) 1:L1num 2:L1den 3:L0num 4:L0den
__device__ double g_negsum[BB];      // per-batch sum of cls-ce over negatives
__device__ int    g_npos[BB];
__device__ int    g_nneg[BB];
__device__ unsigned g_done;

__device__ __forceinline__ float c4(const float4 v, int q) {
    return q == 0 ? v.x : q == 1 ? v.y : q == 2 ? v.z : v.w;
}

// ---------------- single fused kernel ---------------------------------------
// 2048 blocks x 128 threads; block = 512 contiguous pixels of one image,
// 4 pixels per thread.
__global__ __launch_bounds__(128, 8) void k_fused(const float* __restrict__ target,
                                                  const float* __restrict__ logits,
                                                  float* __restrict__ out) {
    __shared__ float st[10 * SP];        // padded SoA staged target (~20.8 KB)
    __shared__ float shr[6][4];
    __shared__ int   shc[2][4];
    __shared__ int   s_last;

    const int tid = threadIdx.x;
    const int blk = blockIdx.x;
    const int b   = blk >> 7;            // 128 blocks per batch image
    const int i0  = blk * PXB;
    const int hw0 = (blk & 127) * PXB;
    const int w = tid >> 5, lane = tid & 31;
    const unsigned full = 0xFFFFFFFFu;

    // stage target AoS->SoA: 512 px * 10 floats = 1280 float4, coalesced
    const float4* tg4 = (const float4*)(target + (size_t)i0 * 10);
#pragma unroll
    for (int jj = 0; jj < 10; jj++) {
        const int j = tid + 128 * jj;
        const float4 v = tg4[j];
        const int f0 = 4 * j;
        { int f = f0 + 0, p = f / 10; st[(f - p * 10) * SP + p] = v.x; }
        { int f = f0 + 1, p = f / 10; st[(f - p * 10) * SP + p] = v.y; }
        { int f = f0 + 2, p = f / 10; st[(f - p * 10) * SP + p] = v.z; }
        { int f = f0 + 3, p = f / 10; st[(f - p * 10) * SP + p] = v.w; }
    }
    __syncthreads();

    const float4* lg4 = (const float4*)(logits + (size_t)b * 10 * HWSZ + hw0);

    const float4 lab4 = *(const float4*)(st + 0 * SP + 4 * tid);
    const float4 wt4  = *(const float4*)(st + 1 * SP + 4 * tid);
    const float4 z0v  = lg4[0 * (HWSZ / 4) + tid];
    const float4 z1v  = lg4[1 * (HWSZ / 4) + tid];

    float sw = 0.f, l1n = 0.f, l1d = 0.f, l0n = 0.f, l0d = 0.f, ns = 0.f;
    int cpos = 0, cneg = 0;

    // cls CE over 4 pixels
#pragma unroll
    for (int q = 0; q < 4; q++) {
        const float lab = c4(lab4, q);
        const bool pos = lab > 0.0f;
        const bool neg = lab == 0.0f;
        cpos += pos; cneg += neg;
        const float z0 = c4(z0v, q);
        const float z1 = c4(z1v, q);
        const float e  = __expf(-fabsf(z1 - z0));
        const float ce = __logf(1.0f + e) + fmaxf(z0, z1) - (pos ? z1 : z0);
        sw += ce * c4(wt4, q);
        if (neg) ns += ce;
    }

    // link CE over 4 neighbours x 4 pixels
#pragma unroll
    for (int n = 0; n < 4; n++) {
        const float4 a4  = lg4[(2 + n) * (HWSZ / 4) + tid];
        const float4 cc4 = lg4[(6 + n) * (HWSZ / 4) + tid];
        const float4 ll4 = *(const float4*)(st + (2 + n) * SP + 4 * tid);
        const float4 lw4 = *(const float4*)(st + (6 + n) * SP + 4 * tid);
#pragma unroll
        for (int q = 0; q < 4; q++) {
            const float a  = c4(a4, q);
            const float c  = c4(cc4, q);
            const bool  li = c4(ll4, q) != 0.0f;
            const float lw = c4(lw4, q);
            const float ee = __expf(-fabsf(c - a));
            const float lce = __logf(1.0f + ee) + fmaxf(a, c) - (li ? c : a);
            if (li) { l1n += lce * lw; l1d += lw; }
            else    { l0n += lce * lw; l0d += lw; }
        }
    }

    // -------- block reduction: 6 floats + 2 counts --------------------------
    float v0 = sw, v1 = l1n, v2 = l1d, v3 = l0n, v4 = l0d, v5 = ns;
    int ip = cpos, in_ = cneg;
#pragma unroll
    for (int off = 16; off; off >>= 1) {
        v0 += __shfl_down_sync(full, v0, off);
        v1 += __shfl_down_sync(full, v1, off);
        v2 += __shfl_down_sync(full, v2, off);
        v3 += __shfl_down_sync(full, v3, off);
        v4 += __shfl_down_sync(full, v4, off);
        v5 += __shfl_down_sync(full, v5, off);
        ip += __shfl_down_sync(full, ip, off);
        in_ += __shfl_down_sync(full, in_, off);
    }
    if (lane == 0) {
        shr[0][w] = v0; shr[1][w] = v1; shr[2][w] = v2;
        shr[3][w] = v3; shr[4][w] = v4; shr[5][w] = v5;
        shc[0][w] = ip; shc[1][w] = in_;
    }
    __syncthreads();

    if (tid == 0) {
        float t0 = 0, t1 = 0, t2 = 0, t3 = 0, t4 = 0, t5 = 0;
        int p = 0, nn = 0;
#pragma unroll
        for (int j = 0; j < 4; j++) {
            t0 += shr[0][j]; t1 += shr[1][j]; t2 += shr[2][j];
            t3 += shr[3][j]; t4 += shr[4][j]; t5 += shr[5][j];
            p += shc[0][j];  nn += shc[1][j];
        }
        const int slot = blk & (NACC - 1);
        atomicAdd(&g_acc[0][slot], (double)t0);
        atomicAdd(&g_acc[1][slot], (double)t1);
        atomicAdd(&g_acc[2][slot], (double)t2);
        atomicAdd(&g_acc[3][slot], (double)t3);
        atomicAdd(&g_acc[4][slot], (double)t4);
        atomicAdd(&g_negsum[b], (double)t5);
        atomicAdd(&g_npos[b], p);
        atomicAdd(&g_nneg[b], nn);
        __threadfence();
        const unsigned prev = atomicAdd(&g_done, 1u);
        s_last = (prev == NBLK - 1);
    }
    __syncthreads();
    if (!s_last) return;

    // =================== tail: last block only ===============================
    __threadfence();
    __shared__ double   sels[BB];
    __shared__ long long nsels[BB];
    __shared__ unsigned s_slowmask;
    __shared__ int      hist[256];
    __shared__ unsigned s_pref;
    __shared__ int      s_k;
    __shared__ float    ssum[4];
    __shared__ int      scnt[4];

    if (tid == 0) s_slowmask = 0u;
    __syncthreads();

    if (tid < BB) {
        const int np = __ldcg(&g_npos[tid]);
        const int nn = __ldcg(&g_nneg[tid]);
        long long k = 3ll * np; if ((long long)nn < k) k = nn;
        if (np == 0 || k == 0 || k == (long long)nn) {
            // selected == all negatives (threshold is max neg score, or use_all)
            sels[tid]  = __ldcg(&g_negsum[tid]);
            nsels[tid] = nn;
        } else {
            sels[tid] = 0.0; nsels[tid] = 0;
            atomicOr(&s_slowmask, 1u << tid);
        }
    }
    __syncthreads();

    // generic slow path (0 < k < nneg): recompute scores, radix-select, sum.
    unsigned slow = s_slowmask;
    while (slow) {
        const int bb = __ffs(slow) - 1;
        slow &= slow - 1;
        const int np = __ldcg(&g_npos[bb]);
        const int nn = __ldcg(&g_nneg[bb]);
        long long k = 3ll * np; if ((long long)nn < k) k = nn;

        float* sc = g_masked  + ((size_t)bb << 16);
        float* cl = g_clsloss + ((size_t)bb << 16);
        const float* lgz0 = logits + (size_t)bb * 10 * HWSZ;
        const float* lgz1 = lgz0 + HWSZ;
        const float* tgl  = target + (size_t)bb * HWSZ * 10;

        // recompute masked score + cls CE for this batch
        for (int j = tid; j < HWSZ; j += 128) {
            const float lab = tgl[(size_t)j * 10];
            const bool pos = lab > 0.0f;
            const bool neg = lab == 0.0f;
            const float z0 = lgz0[j];
            const float z1 = lgz1[j];
            const float d  = z1 - z0;
            const float e  = __expf(-fabsf(d));
            const float ce = __logf(1.0f + e) + fmaxf(z0, z1) - (pos ? z1 : z0);
            const float r  = __fdividef(1.0f, 1.0f + e);
            const float score = (d > 0.0f) ? e * r : r;   // softmax p0
            sc[j] = neg ? score : __uint_as_float(0x7f800000u);
            cl[j] = ce;
        }
        __syncthreads();

        if (tid == 0) { s_pref = 0u; s_k = (int)k; }
        __syncthreads();
        for (int shift = 24; shift >= 0; shift -= 8) {
            hist[tid] = 0; hist[tid + 128] = 0;
            __syncthreads();
            const unsigned pref = s_pref;
            const unsigned mask = (shift == 24) ? 0u : (0xFFFFFFFFu << (shift + 8));
            for (int j = tid; j < HWSZ; j += 128) {
                const unsigned u = __float_as_uint(sc[j]);
                if ((u & mask) == pref) atomicAdd(&hist[(u >> shift) & 0xFFu], 1);
            }
            __syncthreads();
            if (tid == 0) {
                int kk = s_k, cum = 0; unsigned dd = 255;
                for (int v = 0; v < 256; v++) {
                    const int h = hist[v];
                    if (cum + h >= kk) { dd = (unsigned)v; s_k = kk - cum; break; }
                    cum += h;
                }
                s_pref = pref | (dd << shift);
            }
            __syncthreads();
        }
        const float thr = __uint_as_float(s_pref);
        float sum = 0.f; int cnt = 0;
        for (int j = tid; j < HWSZ; j += 128) {
            const float m = sc[j];
            if (m <= thr) { sum += cl[j]; cnt++; }
        }
#pragma unroll
        for (int off = 16; off; off >>= 1) {
            sum += __shfl_down_sync(full, sum, off);
            cnt += __shfl_down_sync(full, cnt, off);
        }
        if (lane == 0) { ssum[w] = sum; scnt[w] = cnt; }
        __syncthreads();
        if (tid == 0) {
            float t = 0; int c = 0;
#pragma unroll
            for (int j = 0; j < 4; j++) { t += ssum[j]; c += scnt[j]; }
            sels[bb] = (double)t; nsels[bb] = c;
        }
        __syncthreads();
    }

    // -------- finalize (warp 0) ---------------------------------------------
    if (tid < 32) {
        double a[5];
#pragma unroll
        for (int r = 0; r < 5; r++) {
            double v = (lane < NACC) ? __ldcg(&g_acc[r][lane]) : 0.0;
#pragma unroll
            for (int off = 16; off; off >>= 1) v += __shfl_down_sync(full, v, off);
            a[r] = v;
        }
        int np = (lane < BB) ? __ldcg(&g_npos[lane]) : 0;
        double ss = (lane < BB) ? sels[lane] : 0.0;
        long long nsl = (lane < BB) ? nsels[lane] : 0ll;
#pragma unroll
        for (int off = 16; off; off >>= 1) {
            np  += __shfl_down_sync(full, np, off);
            ss  += __shfl_down_sync(full, ss, off);
            nsl += __shfl_down_sync(full, nsl, off);
        }
        if (lane == 0) {
            const double cls = (a[0] + ss) / ((double)np + (double)nsl);
            double link = 0.0;
            if (np > 0) {
                const double l1 = (a[2] != 0.0) ? a[1] / a[2] : 0.0;
                const double l0 = (a[4] != 0.0) ? a[3] / a[4] : 0.0;
                link = l1 + l0;
            }
            out[0] = (float)(cls * 2.0);
            out[1] = (float)link;
        }
    }
    __syncthreads();

    // -------- reset global state for next graph replay ----------------------
    if (tid < 5 * NACC) ((double*)g_acc)[tid] = 0.0;
    if (tid >= 80 && tid < 80 + BB) g_negsum[tid - 80] = 0.0;
    if (tid >= 96 && tid < 96 + BB) { g_npos[tid - 96] = 0; g_nneg[tid - 96] = 0; }
    if (tid == 112) g_done = 0u;
}

// ---------------- launcher ----------------------------------------------------
extern "C" void kernel_launch(void* const* d_in, const int* in_sizes, int n_in,
                              void* d_out, int out_size) {
    const float* target = (const float*)d_in[0];
    const float* logits = (const float*)d_in[1];
    float* out = (float*)d_out;

    k_fused<<<NBLK, 128>>>(target, logits, out);
}

// round 6
// speedup vs baseline: 4.2640x; 1.1100x over previous
#include <cuda_runtime.h>
#include <cstdint>

#define BB    16
#define HWSZ  65536
#define NPIX  (BB * HWSZ)
#define NACC  16
#define PXB   512                  // pixels per block
#define NBLK  (NPIX / PXB)         // 2048 blocks

// ---------------- device-global scratch (zero-initialized at load) ---------
__device__ float  g_masked[NPIX];    // slow path only
__device__ float  g_clsloss[NPIX];   // slow path only
__device__ double g_acc[5][NACC];    // 0:Sw(ce*w) 1:L1num 2:L1den 3:L0num 4:L0den
__device__ double g_negsum[BB];      // per-batch sum of cls-ce over negatives
__device__ int    g_npos[BB];
__device__ int    g_nneg[BB];
__device__ unsigned g_done;

__device__ __forceinline__ float comp2(const float2 v, int q) { return q ? v.y : v.x; }

// ---------------- single fused kernel ---------------------------------------
// 2048 blocks x 256 threads; block = 512 contiguous pixels of one image,
// 2 pixels per thread. Target staged AoS via cp.async; logits LDGs overlap.
__global__ __launch_bounds__(256) void k_fused(const float* __restrict__ target,
                                               const float* __restrict__ logits,
                                               float* __restrict__ out) {
    __shared__ float4 st4[PXB * 10 / 4];   // AoS staged target, 20 KB, 16B-aligned
    __shared__ float  shr[6][8];
    __shared__ int    shc[2][8];
    __shared__ int    s_last;
    float* st = (float*)st4;

    const int tid = threadIdx.x;
    const int blk = blockIdx.x;
    const int b   = blk >> 7;              // 128 blocks per batch image
    const int i0  = blk * PXB;
    const int hw0 = (blk & 127) * PXB;
    const int w = tid >> 5, lane = tid & 31;
    const unsigned full = 0xFFFFFFFFu;

    // ---- async stage target (AoS, as-is): 1280 float4, 5 per thread --------
    const float4* tg4 = (const float4*)(target + (size_t)i0 * 10);
    const unsigned sbase = (unsigned)__cvta_generic_to_shared(st4);
#pragma unroll
    for (int jj = 0; jj < 5; jj++) {
        const int j = tid + 256 * jj;
        asm volatile("cp.async.cg.shared.global [%0], [%1], 16;\n"
                     :: "r"(sbase + j * 16), "l"(tg4 + j));
    }
    asm volatile("cp.async.commit_group;\n");

    // ---- logits loads issue while the copy is in flight ---------------------
    const float2* lg2 = (const float2*)(logits + (size_t)b * 10 * HWSZ + hw0);
    float2 z2[10];
#pragma unroll
    for (int c = 0; c < 10; c++) z2[c] = lg2[c * (HWSZ / 2) + tid];

    asm volatile("cp.async.wait_group 0;\n");
    __syncthreads();

    // ---- conflict-free AoS readback: 80B per thread = 5 LDS.128 ------------
    float4 tv4[5];
#pragma unroll
    for (int k = 0; k < 5; k++) tv4[k] = st4[tid * 5 + k];
    const float* tv = (const float*)tv4;   // tv[10q + f] = field f of pixel q

    float sw = 0.f, l1n = 0.f, l1d = 0.f, l0n = 0.f, l0d = 0.f, ns = 0.f;
    int cpos = 0, cneg = 0;

#pragma unroll
    for (int q = 0; q < 2; q++) {
        const float lab = tv[10 * q + 0];
        const float wt  = tv[10 * q + 1];
        const bool pos = lab > 0.0f;
        const bool neg = lab == 0.0f;
        cpos += pos; cneg += neg;

        const float z0 = comp2(z2[0], q);
        const float z1 = comp2(z2[1], q);
        const float e  = __expf(-fabsf(z1 - z0));
        const float ce = __logf(1.0f + e) + fmaxf(z0, z1) - (pos ? z1 : z0);
        sw += ce * wt;
        if (neg) ns += ce;

#pragma unroll
        for (int n = 0; n < 4; n++) {
            const float a  = comp2(z2[2 + n], q);
            const float c  = comp2(z2[6 + n], q);
            const bool  li = tv[10 * q + 2 + n] != 0.0f;
            const float lw = tv[10 * q + 6 + n];
            const float ee  = __expf(-fabsf(c - a));
            const float lce = __logf(1.0f + ee) + fmaxf(a, c) - (li ? c : a);
            if (li) { l1n += lce * lw; l1d += lw; }
            else    { l0n += lce * lw; l0d += lw; }
        }
    }

    // -------- block reduction: 6 floats + 2 counts --------------------------
    float v0 = sw, v1 = l1n, v2 = l1d, v3 = l0n, v4 = l0d, v5 = ns;
    int ip = cpos, in_ = cneg;
#pragma unroll
    for (int off = 16; off; off >>= 1) {
        v0 += __shfl_down_sync(full, v0, off);
        v1 += __shfl_down_sync(full, v1, off);
        v2 += __shfl_down_sync(full, v2, off);
        v3 += __shfl_down_sync(full, v3, off);
        v4 += __shfl_down_sync(full, v4, off);
        v5 += __shfl_down_sync(full, v5, off);
        ip += __shfl_down_sync(full, ip, off);
        in_ += __shfl_down_sync(full, in_, off);
    }
    if (lane == 0) {
        shr[0][w] = v0; shr[1][w] = v1; shr[2][w] = v2;
        shr[3][w] = v3; shr[4][w] = v4; shr[5][w] = v5;
        shc[0][w] = ip; shc[1][w] = in_;
    }
    __syncthreads();

    if (tid == 0) {
        float t0 = 0, t1 = 0, t2 = 0, t3 = 0, t4 = 0, t5 = 0;
        int p = 0, nn = 0;
#pragma unroll
        for (int j = 0; j < 8; j++) {
            t0 += shr[0][j]; t1 += shr[1][j]; t2 += shr[2][j];
            t3 += shr[3][j]; t4 += shr[4][j]; t5 += shr[5][j];
            p += shc[0][j];  nn += shc[1][j];
        }
        const int slot = blk & (NACC - 1);
        atomicAdd(&g_acc[0][slot], (double)t0);
        atomicAdd(&g_acc[1][slot], (double)t1);
        atomicAdd(&g_acc[2][slot], (double)t2);
        atomicAdd(&g_acc[3][slot], (double)t3);
        atomicAdd(&g_acc[4][slot], (double)t4);
        atomicAdd(&g_negsum[b], (double)t5);
        atomicAdd(&g_npos[b], p);
        atomicAdd(&g_nneg[b], nn);
        __threadfence();
        const unsigned prev = atomicAdd(&g_done, 1u);
        s_last = (prev == NBLK - 1);
    }
    __syncthreads();
    if (!s_last) return;

    // =================== tail: last block only ===============================
    __threadfence();
    __shared__ double   sels[BB];
    __shared__ long long nsels[BB];
    __shared__ unsigned s_slowmask;
    __shared__ int      hist[256];
    __shared__ unsigned s_pref;
    __shared__ int      s_k;
    __shared__ float    ssum[8];
    __shared__ int      scnt[8];

    if (tid == 0) s_slowmask = 0u;
    __syncthreads();

    if (tid < BB) {
        const int np = __ldcg(&g_npos[tid]);
        const int nn = __ldcg(&g_nneg[tid]);
        long long k = 3ll * np; if ((long long)nn < k) k = nn;
        if (np == 0 || k == 0 || k == (long long)nn) {
            // selected == all negatives (threshold = max neg score, or use_all)
            sels[tid]  = __ldcg(&g_negsum[tid]);
            nsels[tid] = nn;
        } else {
            sels[tid] = 0.0; nsels[tid] = 0;
            atomicOr(&s_slowmask, 1u << tid);
        }
    }
    __syncthreads();

    // generic slow path (0 < k < nneg): recompute scores, radix-select, sum.
    unsigned slow = s_slowmask;
    while (slow) {
        const int bb = __ffs(slow) - 1;
        slow &= slow - 1;
        const int np = __ldcg(&g_npos[bb]);
        const int nn = __ldcg(&g_nneg[bb]);
        long long k = 3ll * np; if ((long long)nn < k) k = nn;

        float* sc = g_masked  + ((size_t)bb << 16);
        float* cl = g_clsloss + ((size_t)bb << 16);
        const float* lgz0 = logits + (size_t)bb * 10 * HWSZ;
        const float* lgz1 = lgz0 + HWSZ;
        const float* tgl  = target + (size_t)bb * HWSZ * 10;

        for (int j = tid; j < HWSZ; j += 256) {
            const float lab = tgl[(size_t)j * 10];
            const bool pos = lab > 0.0f;
            const bool neg = lab == 0.0f;
            const float z0 = lgz0[j];
            const float z1 = lgz1[j];
            const float d  = z1 - z0;
            const float e  = __expf(-fabsf(d));
            const float ce = __logf(1.0f + e) + fmaxf(z0, z1) - (pos ? z1 : z0);
            const float r  = __fdividef(1.0f, 1.0f + e);
            const float score = (d > 0.0f) ? e * r : r;   // softmax p0
            sc[j] = neg ? score : __uint_as_float(0x7f800000u);
            cl[j] = ce;
        }
        __syncthreads();

        if (tid == 0) { s_pref = 0u; s_k = (int)k; }
        __syncthreads();
        for (int shift = 24; shift >= 0; shift -= 8) {
            hist[tid & 255] = 0;
            __syncthreads();
            const unsigned pref = s_pref;
            const unsigned mask = (shift == 24) ? 0u : (0xFFFFFFFFu << (shift + 8));
            for (int j = tid; j < HWSZ; j += 256) {
                const unsigned u = __float_as_uint(sc[j]);
                if ((u & mask) == pref) atomicAdd(&hist[(u >> shift) & 0xFFu], 1);
            }
            __syncthreads();
            if (tid == 0) {
                int kk = s_k, cum = 0; unsigned dd = 255;
                for (int v = 0; v < 256; v++) {
                    const int h = hist[v];
                    if (cum + h >= kk) { dd = (unsigned)v; s_k = kk - cum; break; }
                    cum += h;
                }
                s_pref = pref | (dd << shift);
            }
            __syncthreads();
        }
        const float thr = __uint_as_float(s_pref);
        float sum = 0.f; int cnt = 0;
        for (int j = tid; j < HWSZ; j += 256) {
            const float m = sc[j];
            if (m <= thr) { sum += cl[j]; cnt++; }
        }
#pragma unroll
        for (int off = 16; off; off >>= 1) {
            sum += __shfl_down_sync(full, sum, off);
            cnt += __shfl_down_sync(full, cnt, off);
        }
        if (lane == 0) { ssum[w] = sum; scnt[w] = cnt; }
        __syncthreads();
        if (tid == 0) {
            float t = 0; int c = 0;
#pragma unroll
            for (int j = 0; j < 8; j++) { t += ssum[j]; c += scnt[j]; }
            sels[bb] = (double)t; nsels[bb] = c;
        }
        __syncthreads();
    }

    // -------- finalize (warp 0) ---------------------------------------------
    if (tid < 32) {
        double a[5];
#pragma unroll
        for (int r = 0; r < 5; r++) {
            double v = (lane < NACC) ? __ldcg(&g_acc[r][lane]) : 0.0;
#pragma unroll
            for (int off = 16; off; off >>= 1) v += __shfl_down_sync(full, v, off);
            a[r] = v;
        }
        int np = (lane < BB) ? __ldcg(&g_npos[lane]) : 0;
        double ss = (lane < BB) ? sels[lane] : 0.0;
        long long nsl = (lane < BB) ? nsels[lane] : 0ll;
#pragma unroll
        for (int off = 16; off; off >>= 1) {
            np  += __shfl_down_sync(full, np, off);
            ss  += __shfl_down_sync(full, ss, off);
            nsl += __shfl_down_sync(full, nsl, off);
        }
        if (lane == 0) {
            const double cls = (a[0] + ss) / ((double)np + (double)nsl);
            double link = 0.0;
            if (np > 0) {
                const double l1 = (a[2] != 0.0) ? a[1] / a[2] : 0.0;
                const double l0 = (a[4] != 0.0) ? a[3] / a[4] : 0.0;
                link = l1 + l0;
            }
            out[0] = (float)(cls * 2.0);
            out[1] = (float)link;
        }
    }
    __syncthreads();

    // -------- reset global state for next graph replay ----------------------
    if (tid < 5 * NACC) ((double*)g_acc)[tid] = 0.0;
    if (tid >= 96 && tid < 96 + BB) g_negsum[tid - 96] = 0.0;
    if (tid >= 128 && tid < 128 + BB) { g_npos[tid - 128] = 0; g_nneg[tid - 128] = 0; }
    if (tid == 160) g_done = 0u;
}

// ---------------- launcher ----------------------------------------------------
extern "C" void kernel_launch(void* const* d_in, const int* in_sizes, int n_in,
                              void* d_out, int out_size) {
    const float* target = (const float*)d_in[0];
    const float* logits = (const float*)d_in[1];
    float* out = (float*)d_out;

    k_fused<<<NBLK, 256>>>(target, logits, out);
}